// round 14
// baseline (speedup 1.0000x reference)
#include <cuda_runtime.h>

#define Nn 200000
#define Ee 600000
#define Gg 1024
#define Hh 512
#define PAD 32   // 32 ints = 128B: one atomic counter per L2 line

typedef unsigned long long u64;

// ---------------- scratch (device globals; no allocation) ----------------
__device__ float d_Sn[Gg * Hh];
__device__ float d_Se[Gg * Hh];
__device__ float d_T1[Gg * Hh];
__device__ float d_X1[Gg * Hh];
__device__ float d_X2[Gg * Hh];
__device__ int   d_hist[Gg * PAD];
__device__ int   d_cursor[Gg * PAD];
__device__ int   d_off[Gg + 1];
__device__ int   d_cntn[Gg];
__device__ int   d_ge[Ee];
__device__ int   d_eord[Ee];

// ---------------- packed f32x2 helpers (sm_103a) ----------------
__device__ __forceinline__ u64 pk2(float lo, float hi) {
    u64 r; asm("mov.b64 %0,{%1,%2};" : "=l"(r) : "f"(lo), "f"(hi)); return r;
}
__device__ __forceinline__ u64 bc2(float v) { return pk2(v, v); }
__device__ __forceinline__ void up2(u64 v, float& lo, float& hi) {
    asm("mov.b64 {%0,%1},%2;" : "=f"(lo), "=f"(hi) : "l"(v));
}
__device__ __forceinline__ u64 fma2(u64 a, u64 b, u64 c) {
    u64 d; asm("fma.rn.f32x2 %0,%1,%2,%3;" : "=l"(d) : "l"(a), "l"(b), "l"(c)); return d;
}
__device__ __forceinline__ u64 add2(u64 a, u64 b) {
    u64 d; asm("add.rn.f32x2 %0,%1,%2;" : "=l"(d) : "l"(a), "l"(b)); return d;
}
__device__ __forceinline__ u64 mul2(u64 a, u64 b) {
    u64 d; asm("mul.rn.f32x2 %0,%1,%2;" : "=l"(d) : "l"(a), "l"(b)); return d;
}
__device__ __forceinline__ float rcpf(float x) {
    float r; asm("rcp.approx.f32 %0,%1;" : "=f"(r) : "f"(x)); return r;
}
__device__ __forceinline__ float ex2f(float x) {
    float r; asm("ex2.approx.f32 %0,%1;" : "=f"(r) : "f"(x)); return r;
}

// Packed GELU taking PRE-SCALED input t = x/sqrt(2) on both lanes.
// gelu(x) = 0.70710678*t*(1+erf(t)); erf via A&S 7.1.26 (abs err <=1.5e-7)
__device__ __forceinline__ u64 gelu2t(u64 t2) {
    const u64 ABS = 0x7FFFFFFF7FFFFFFFull;
    const u64 SGN = 0x8000000080000000ull;
    u64 a2 = t2 & ABS;
    u64 den = fma2(bc2(0.3275911f), a2, bc2(1.0f));
    float dn0, dn1; up2(den, dn0, dn1);
    u64 dd = pk2(rcpf(dn0), rcpf(dn1));
    u64 p = fma2(bc2(1.061405429f), dd, bc2(-1.453152027f));
    p = fma2(p, dd, bc2(1.421413741f));
    p = fma2(p, dd, bc2(-0.284496736f));
    p = fma2(p, dd, bc2(0.254829592f));
    p = mul2(p, dd);
    u64 m2 = mul2(a2, a2);
    u64 ml = mul2(m2, bc2(-1.4426950408889634f));
    float q0, q1; up2(ml, q0, q1);
    u64 e2 = pk2(ex2f(q0), ex2f(q1));
    u64 erf = fma2(p ^ SGN, e2, bc2(1.0f));   // 1 - p*e >= 0
    erf = erf | (t2 & SGN);                    // copysign
    u64 ct = mul2(t2, bc2(0.70710678118654752440f));
    return fma2(ct, erf, ct);                  // c*t*(1+erf)
}

// scalar GELU on pre-scaled t = x/sqrt(2)
__device__ __forceinline__ float gelu_ft(float t) {
    float a = fabsf(t);
    float d = rcpf(fmaf(0.3275911f, a, 1.0f));
    float p = fmaf(1.061405429f, d, -1.453152027f);
    p = fmaf(p, d, 1.421413741f);
    p = fmaf(p, d, -0.284496736f);
    p = fmaf(p, d, 0.254829592f);
    p = p * d;
    float e = ex2f(-a * a * 1.4426950408889634f);
    float erfv = copysignf(fmaf(-p, e, 1.0f), t);
    float ct = 0.70710678118654752440f * t;
    return fmaf(ct, erfv, ct);
}

// scalar GELU on raw x (graph MLP epilogue)
__device__ __forceinline__ float gelu_f(float x) {
    return gelu_ft(x * 0.70710678118654752440f);
}

// ---------------- edge counting sort (128B-padded counters) ----------------
__global__ void k_zero() {
    int t = blockIdx.x * blockDim.x + threadIdx.x;
    if (t < Gg * PAD) d_hist[t] = 0;
}

__global__ void k_hist(const int* __restrict__ ei, const int* __restrict__ bidx) {
    int e = blockIdx.x * blockDim.x + threadIdx.x;
    if (e < Ee) {
        int g = bidx[ei[e]];
        d_ge[e] = g;
        atomicAdd(&d_hist[g * PAD], 1);
    }
}

__global__ void k_scan() {
    __shared__ int tmp[Gg];
    int t = threadIdx.x;
    int h = d_hist[t * PAD];
    tmp[t] = h;
    __syncthreads();
    for (int off = 1; off < Gg; off <<= 1) {
        int v = (t >= off) ? tmp[t - off] : 0;
        __syncthreads();
        tmp[t] += v;
        __syncthreads();
    }
    d_off[t + 1] = tmp[t];
    if (t == 0) d_off[0] = 0;
    d_cursor[t * PAD] = tmp[t] - h;
}

__global__ void k_scatter() {
    int e = blockIdx.x * blockDim.x + threadIdx.x;
    if (e < Ee) {
        int g = d_ge[e];
        int p = atomicAdd(&d_cursor[g * PAD], 1);
        d_eord[p] = e;
    }
}

// ---------------- fused node layer-1 + BN + GELU + segment reduce ------------
// grid = 2048: graph = blockIdx>>1, column half = blockIdx&1. Thread owns ONE
// column j. f32x2 lanes = TWO NODES at column j; weights are (w,w) in regs
// (broadcast once), features come from a feature-major shared tile where
// pk2(v.x,v.y) of one LDS.128 is an adjacent-register rename, not a broadcast.
#define NSTR 36   // node tile stride (32 nodes + pad), 144B = 16B-aligned rows
__global__ void __launch_bounds__(256) k_node(
    const float* __restrict__ nf, const float* __restrict__ dp,
    const int* __restrict__ ny, const int* __restrict__ bidx,
    const float* __restrict__ w1, const float* __restrict__ b1,
    const float* __restrict__ g1, const float* __restrict__ be1)
{
    __shared__ __align__(16) float s_n[32 * NSTR];   // [feature][node]
    __shared__ float s_w9[9 * 256];                  // pre-scaled class weights, this col half
    __shared__ __align__(8) float s_dp[32];
    __shared__ int   s_y[32];

    int g = blockIdx.x >> 1;
    int t = threadIdx.x;
    int j = ((blockIdx.x & 1) << 8) + t;

    const float inv = rsqrtf(1.0f + 1e-5f);
    const float RS2 = 0.70710678118654752440f;
    float sc = g1[j] * inv;
    float ws = sc * RS2;

    u64 wn[32];
#pragma unroll
    for (int k = 0; k < 32; k++) wn[k] = bc2(w1[k * Hh + j] * ws);
#pragma unroll
    for (int c = 0; c < 9; c++) s_w9[c * 256 + t] = w1[(32 + c) * Hh + j] * ws;
    float bjs = (b1[j] * sc + be1[j]) * RS2;
    u64 bj2 = bc2(bjs);

    int lo = 0, hi = Nn;
    while (lo < hi) { int m = (lo + hi) >> 1; if (bidx[m] < g) lo = m + 1; else hi = m; }
    int s0i = lo;
    hi = Nn;
    while (lo < hi) { int m = (lo + hi) >> 1; if (bidx[m] < g + 1) lo = m + 1; else hi = m; }
    int s1i = lo;

    u64 acc2 = 0;
    float tacc = 0.0f;
    for (int base = s0i; base < s1i; base += 32) {
        int cnt = min(32, s1i - base);
        __syncthreads();
        {
            int row = t >> 3, q = t & 7;
            if (row < cnt) {
                float4 v = ((const float4*)nf)[(base + row) * 8 + q];
                int k0 = q * 4;
                s_n[(k0 + 0) * NSTR + row] = v.x;
                s_n[(k0 + 1) * NSTR + row] = v.y;
                s_n[(k0 + 2) * NSTR + row] = v.z;
                s_n[(k0 + 3) * NSTR + row] = v.w;
            }
            if (t < cnt) { s_dp[t] = dp[base + t]; s_y[t] = ny[base + t]; }
        }
        __syncthreads();
        int n = 0;
        for (; n + 4 <= cnt; n += 4) {
            u64 a0 = bj2, a1 = 0, b0 = bj2, b1_ = 0;
#pragma unroll
            for (int k = 0; k < 32; k += 2) {
                float4 v0 = *(const float4*)&s_n[k * NSTR + n];
                float4 v1 = *(const float4*)&s_n[(k + 1) * NSTR + n];
                a0  = fma2(pk2(v0.x, v0.y), wn[k],     a0);
                b0  = fma2(pk2(v0.z, v0.w), wn[k],     b0);
                a1  = fma2(pk2(v1.x, v1.y), wn[k + 1], a1);
                b1_ = fma2(pk2(v1.z, v1.w), wn[k + 1], b1_);
            }
            u64 WA = pk2(s_w9[s_y[n] * 256 + t],     s_w9[s_y[n + 1] * 256 + t]);
            u64 WB = pk2(s_w9[s_y[n + 2] * 256 + t], s_w9[s_y[n + 3] * 256 + t]);
            a0 = fma2(*(const u64*)&s_dp[n],     WA, a0);
            b0 = fma2(*(const u64*)&s_dp[n + 2], WB, b0);
            acc2 = add2(acc2, gelu2t(add2(a0, a1)));
            acc2 = add2(acc2, gelu2t(add2(b0, b1_)));
        }
        for (; n + 2 <= cnt; n += 2) {
            u64 a0 = bj2, a1 = 0;
#pragma unroll
            for (int k = 0; k < 32; k += 2) {
                a0 = fma2(*(const u64*)&s_n[k * NSTR + n],       wn[k],     a0);
                a1 = fma2(*(const u64*)&s_n[(k + 1) * NSTR + n], wn[k + 1], a1);
            }
            u64 WA = pk2(s_w9[s_y[n] * 256 + t], s_w9[s_y[n + 1] * 256 + t]);
            a0 = fma2(*(const u64*)&s_dp[n], WA, a0);
            acc2 = add2(acc2, gelu2t(add2(a0, a1)));
        }
        if (n < cnt) {   // single tail: lane1 reads in-bounds pad garbage, discarded
            u64 a0 = bj2, a1 = 0;
#pragma unroll
            for (int k = 0; k < 32; k += 2) {
                a0 = fma2(*(const u64*)&s_n[k * NSTR + n],       wn[k],     a0);
                a1 = fma2(*(const u64*)&s_n[(k + 1) * NSTR + n], wn[k + 1], a1);
            }
            float t0, t1; up2(add2(a0, a1), t0, t1);
            t0 += s_dp[n] * s_w9[s_y[n] * 256 + t];
            tacc += gelu_ft(t0);
        }
    }
    float r0, r1; up2(acc2, r0, r1);
    d_Sn[g * Hh + j] = r0 + r1 + tacc;
    if (t == 0 && (blockIdx.x & 1) == 0) d_cntn[g] = s1i - s0i;
}

// ---------------- fused edge layer-1 + BN + GELU + segment reduce ------------
#define ESTR 68   // edge tile stride (64 edges + pad), 272B = 16B-aligned rows
__global__ void __launch_bounds__(256) k_edge(
    const float* __restrict__ ef,
    const float* __restrict__ w1, const float* __restrict__ b1,
    const float* __restrict__ g1, const float* __restrict__ be1)
{
    __shared__ __align__(16) float s_e[16 * ESTR];   // [feature][edge]

    int g = blockIdx.x >> 1;
    int t = threadIdx.x;
    int j = ((blockIdx.x & 1) << 8) + t;

    const float inv = rsqrtf(1.0f + 1e-5f);
    const float RS2 = 0.70710678118654752440f;
    float sc = g1[j] * inv;
    float ws = sc * RS2;

    u64 we[16];
#pragma unroll
    for (int k = 0; k < 16; k++) we[k] = bc2(w1[k * Hh + j] * ws);
    u64 bj2 = bc2((b1[j] * sc + be1[j]) * RS2);

    int s0i = d_off[g], s1i = d_off[g + 1];
    u64 acc2 = 0;
    float tacc = 0.0f;
    for (int base = s0i; base < s1i; base += 64) {
        int cnt = min(64, s1i - base);
        __syncthreads();
        {
            int row = t >> 2, q = t & 3;
            if (row < cnt) {
                float4 v = ((const float4*)ef)[d_eord[base + row] * 4 + q];
                int k0 = q * 4;
                s_e[(k0 + 0) * ESTR + row] = v.x;
                s_e[(k0 + 1) * ESTR + row] = v.y;
                s_e[(k0 + 2) * ESTR + row] = v.z;
                s_e[(k0 + 3) * ESTR + row] = v.w;
            }
        }
        __syncthreads();
        int n = 0;
        for (; n + 4 <= cnt; n += 4) {
            u64 a0 = bj2, a1 = 0, b0 = bj2, b1_ = 0;
#pragma unroll
            for (int k = 0; k < 16; k += 2) {
                float4 v0 = *(const float4*)&s_e[k * ESTR + n];
                float4 v1 = *(const float4*)&s_e[(k + 1) * ESTR + n];
                a0  = fma2(pk2(v0.x, v0.y), we[k],     a0);
                b0  = fma2(pk2(v0.z, v0.w), we[k],     b0);
                a1  = fma2(pk2(v1.x, v1.y), we[k + 1], a1);
                b1_ = fma2(pk2(v1.z, v1.w), we[k + 1], b1_);
            }
            acc2 = add2(acc2, gelu2t(add2(a0, a1)));
            acc2 = add2(acc2, gelu2t(add2(b0, b1_)));
        }
        for (; n + 2 <= cnt; n += 2) {
            u64 a0 = bj2, a1 = 0;
#pragma unroll
            for (int k = 0; k < 16; k += 2) {
                a0 = fma2(*(const u64*)&s_e[k * ESTR + n],       we[k],     a0);
                a1 = fma2(*(const u64*)&s_e[(k + 1) * ESTR + n], we[k + 1], a1);
            }
            acc2 = add2(acc2, gelu2t(add2(a0, a1)));
        }
        if (n < cnt) {
            u64 a0 = bj2, a1 = 0;
#pragma unroll
            for (int k = 0; k < 16; k += 2) {
                a0 = fma2(*(const u64*)&s_e[k * ESTR + n],       we[k],     a0);
                a1 = fma2(*(const u64*)&s_e[(k + 1) * ESTR + n], we[k + 1], a1);
            }
            float t0, t1; up2(add2(a0, a1), t0, t1);
            tacc += gelu_ft(t0);
        }
    }
    float r0, r1; up2(acc2, r0, r1);
    d_Se[g * Hh + j] = r0 + r1 + tacc;
}

// ---------------- graph-level dual GEMM ----------------
__global__ void __launch_bounds__(256) k_t1(
    const float* __restrict__ gf,
    const float* __restrict__ nfw2, const float* __restrict__ nfb2,
    const float* __restrict__ efw2, const float* __restrict__ efb2)
{
    __shared__ float As[16][64];
    __shared__ float Bs[16][64];
    int row0 = blockIdx.y * 64, col0 = blockIdx.x * 64;
    int tid = threadIdx.x, ty = tid >> 4, tx = tid & 15;
    float acc[4][4] = {};

    for (int pass = 0; pass < 2; pass++) {
        const float* A = pass ? d_Se : d_Sn;
        const float* B = pass ? efw2 : nfw2;
        for (int k0 = 0; k0 < Hh; k0 += 16) {
#pragma unroll
            for (int i = 0; i < 4; i++) {
                int idx = tid + i * 256;
                int r = idx >> 4, kk = idx & 15;
                As[kk][r] = A[(row0 + r) * Hh + k0 + kk];
                int kb = idx >> 6, c = idx & 63;
                Bs[kb][c] = B[(k0 + kb) * Hh + col0 + c];
            }
            __syncthreads();
#pragma unroll
            for (int kk = 0; kk < 16; kk++) {
                float av[4], bv[4];
#pragma unroll
                for (int i = 0; i < 4; i++) av[i] = As[kk][ty * 4 + i];
#pragma unroll
                for (int jx = 0; jx < 4; jx++) bv[jx] = Bs[kk][tx * 4 + jx];
#pragma unroll
                for (int i = 0; i < 4; i++)
#pragma unroll
                    for (int jx = 0; jx < 4; jx++) acc[i][jx] += av[i] * bv[jx];
            }
            __syncthreads();
        }
    }
#pragma unroll
    for (int i = 0; i < 4; i++) {
        int r = row0 + ty * 4 + i;
        float cn = (float)d_cntn[r];
        float ce = (float)(d_off[r + 1] - d_off[r]);
#pragma unroll
        for (int jx = 0; jx < 4; jx++) {
            int c = col0 + tx * 4 + jx;
            d_T1[r * Hh + c] = acc[i][jx] + gf[r * Hh + c] + cn * nfb2[c] + ce * efb2[c];
        }
    }
}

// ---------------- graph MLP block ----------------
__global__ void __launch_bounds__(256) k_mlp(
    int stage,
    const float* __restrict__ W, const float* __restrict__ b,
    const float* __restrict__ gm, const float* __restrict__ be)
{
    const float* A = (stage == 0) ? d_T1 : d_X1;
    float* out = (stage == 0) ? d_X1 : d_X2;

    __shared__ float As[16][64];
    __shared__ float Bs[16][64];
    int row0 = blockIdx.y * 64, col0 = blockIdx.x * 64;
    int tid = threadIdx.x, ty = tid >> 4, tx = tid & 15;
    float acc[4][4] = {};

    for (int k0 = 0; k0 < Hh; k0 += 16) {
#pragma unroll
        for (int i = 0; i < 4; i++) {
            int idx = tid + i * 256;
            int r = idx >> 4, kk = idx & 15;
            As[kk][r] = A[(row0 + r) * Hh + k0 + kk];
            int kb = idx >> 6, c = idx & 63;
            Bs[kb][c] = W[(k0 + kb) * Hh + col0 + c];
        }
        __syncthreads();
#pragma unroll
        for (int kk = 0; kk < 16; kk++) {
            float av[4], bv[4];
#pragma unroll
            for (int i = 0; i < 4; i++) av[i] = As[kk][ty * 4 + i];
#pragma unroll
            for (int jx = 0; jx < 4; jx++) bv[jx] = Bs[kk][tx * 4 + jx];
#pragma unroll
            for (int i = 0; i < 4; i++)
#pragma unroll
                for (int jx = 0; jx < 4; jx++) acc[i][jx] += av[i] * bv[jx];
        }
        __syncthreads();
    }
#pragma unroll
    for (int i = 0; i < 4; i++) {
        int r = row0 + ty * 4 + i;
#pragma unroll
        for (int jx = 0; jx < 4; jx++) {
            int c = col0 + tx * 4 + jx;
            float s = gm[c] * rsqrtf(1.0f + 1e-5f);
            float v = acc[i][jx] * s + b[c] * s + be[c];
            out[r * Hh + c] = gelu_f(v);
        }
    }
}

// ---------------- final Linear 512 -> 2 ----------------
__global__ void __launch_bounds__(256) k_out(
    const float* __restrict__ w3, const float* __restrict__ b3, float* __restrict__ out)
{
    int warp = (blockIdx.x * blockDim.x + threadIdx.x) >> 5;
    int lane = threadIdx.x & 31;
    if (warp >= Gg * 2) return;
    int g = warp >> 1, c = warp & 1;
    const float* x = &d_X2[g * Hh];
    float acc = 0.0f;
    for (int k = lane; k < Hh; k += 32) acc += x[k] * w3[k * 2 + c];
#pragma unroll
    for (int o = 16; o; o >>= 1) acc += __shfl_down_sync(0xffffffffu, acc, o);
    if (lane == 0) out[g * 2 + c] = acc + b3[c];
}

// ---------------- launch ----------------
extern "C" void kernel_launch(void* const* d_in, const int* in_sizes, int n_in,
                              void* d_out, int out_size)
{
    const float* nf    = (const float*)d_in[0];
    const float* ef    = (const float*)d_in[1];
    const float* gf    = (const float*)d_in[2];
    const float* dp    = (const float*)d_in[3];
    const int*   ny    = (const int*)d_in[4];
    const int*   bidx  = (const int*)d_in[5];
    const int*   ei    = (const int*)d_in[6];
    const float* nfw1  = (const float*)d_in[7];
    const float* nfb1  = (const float*)d_in[8];
    const float* nfg1  = (const float*)d_in[9];
    const float* nfbe1 = (const float*)d_in[10];
    const float* nfw2  = (const float*)d_in[11];
    const float* nfb2  = (const float*)d_in[12];
    const float* efw1  = (const float*)d_in[13];
    const float* efb1  = (const float*)d_in[14];
    const float* efg1  = (const float*)d_in[15];
    const float* efbe1 = (const float*)d_in[16];
    const float* efw2  = (const float*)d_in[17];
    const float* efb2  = (const float*)d_in[18];
    const float* ow1   = (const float*)d_in[19];
    const float* ob1   = (const float*)d_in[20];
    const float* og1   = (const float*)d_in[21];
    const float* obe1  = (const float*)d_in[22];
    const float* ow2   = (const float*)d_in[23];
    const float* ob2   = (const float*)d_in[24];
    const float* og2   = (const float*)d_in[25];
    const float* obe2  = (const float*)d_in[26];
    const float* ow3   = (const float*)d_in[27];
    const float* ob3   = (const float*)d_in[28];
    float* out = (float*)d_out;

    k_zero<<<(Gg * PAD + 255) / 256, 256>>>();
    k_hist<<<(Ee + 255) / 256, 256>>>(ei, bidx);
    k_scan<<<1, Gg>>>();
    k_scatter<<<(Ee + 255) / 256, 256>>>();

    k_node<<<2 * Gg, 256>>>(nf, dp, ny, bidx, nfw1, nfb1, nfg1, nfbe1);
    k_edge<<<2 * Gg, 256>>>(ef, efw1, efb1, efg1, efbe1);

    dim3 gdim(Hh / 64, Gg / 64);
    k_t1<<<gdim, 256>>>(gf, nfw2, nfb2, efw2, efb2);
    k_mlp<<<gdim, 256>>>(0, ow1, ob1, og1, obe1);
    k_mlp<<<gdim, 256>>>(1, ow2, ob2, og2, obe2);
    k_out<<<(Gg * 2 * 32) / 256, 256>>>(ow3, ob3, out);
}

// round 17
// speedup vs baseline: 1.1458x; 1.1458x over previous
#include <cuda_runtime.h>

#define Nn 200000
#define Ee 600000
#define Gg 1024
#define Hh 512
#define PAD 32   // 32 ints = 128B: one atomic counter per L2 line

typedef unsigned long long u64;

// ---------------- scratch (device globals; no allocation) ----------------
__device__ float d_Sn[Gg * Hh];
__device__ float d_Se[Gg * Hh];
__device__ float d_T1[Gg * Hh];
__device__ float d_X1[Gg * Hh];
__device__ float d_X2[Gg * Hh];
__device__ int   d_hist[Gg * PAD];
__device__ int   d_cursor[Gg * PAD];
__device__ int   d_off[Gg + 1];
__device__ int   d_cntn[Gg];
__device__ int   d_ge[Ee];
__device__ int   d_eord[Ee];

// ---------------- packed f32x2 helpers (sm_103a) ----------------
__device__ __forceinline__ u64 pk2(float lo, float hi) {
    u64 r; asm("mov.b64 %0,{%1,%2};" : "=l"(r) : "f"(lo), "f"(hi)); return r;
}
__device__ __forceinline__ u64 bc2(float v) { return pk2(v, v); }
__device__ __forceinline__ void up2(u64 v, float& lo, float& hi) {
    asm("mov.b64 {%0,%1},%2;" : "=f"(lo), "=f"(hi) : "l"(v));
}
__device__ __forceinline__ u64 fma2(u64 a, u64 b, u64 c) {
    u64 d; asm("fma.rn.f32x2 %0,%1,%2,%3;" : "=l"(d) : "l"(a), "l"(b), "l"(c)); return d;
}
__device__ __forceinline__ u64 add2(u64 a, u64 b) {
    u64 d; asm("add.rn.f32x2 %0,%1,%2;" : "=l"(d) : "l"(a), "l"(b)); return d;
}
__device__ __forceinline__ u64 mul2(u64 a, u64 b) {
    u64 d; asm("mul.rn.f32x2 %0,%1,%2;" : "=l"(d) : "l"(a), "l"(b)); return d;
}
__device__ __forceinline__ float rcpf(float x) {
    float r; asm("rcp.approx.f32 %0,%1;" : "=f"(r) : "f"(x)); return r;
}
__device__ __forceinline__ float ex2f(float x) {
    float r; asm("ex2.approx.f32 %0,%1;" : "=f"(r) : "f"(x)); return r;
}

// Packed tanh-form GELU on raw x, both lanes:
// gelu(x) = 0.5x(1+tanh(0.7978845608(x+0.044715x^3)))
// tanh(z) = 1 - 2/(e^{2z}+1); e^{2z} via ex2(z*2log2e). Branchless; saturates
// correctly (e^{2z}->inf => rcp->0 => tanh->1; e^{2z}->0 => tanh->-1).
__device__ __forceinline__ u64 gelu2(u64 x2) {
    u64 xx = mul2(x2, x2);
    u64 q  = fma2(bc2(0.03567740813636141f), xx, bc2(0.7978845608028654f));
    u64 z  = mul2(q, x2);
    u64 u  = mul2(z, bc2(2.8853900817779268f));   // 2*log2(e)*z
    float u0, u1; up2(u, u0, u1);
    u64 e2 = pk2(ex2f(u0), ex2f(u1));             // e^{2z}
    u64 dn = add2(e2, bc2(1.0f));
    float d0, d1; up2(dn, d0, d1);
    u64 r2 = pk2(rcpf(d0), rcpf(d1));
    u64 th = fma2(bc2(-2.0f), r2, bc2(1.0f));     // tanh(z)
    u64 hx = mul2(x2, bc2(0.5f));
    return fma2(hx, th, hx);                      // 0.5x(1+tanh)
}

// scalar tanh-form GELU (graph MLP epilogue)
__device__ __forceinline__ float gelu_f(float x) {
    float xx = x * x;
    float q  = fmaf(0.03567740813636141f, xx, 0.7978845608028654f);
    float z  = q * x;
    float e2 = ex2f(z * 2.8853900817779268f);
    float th = fmaf(-2.0f, rcpf(e2 + 1.0f), 1.0f);
    float hx = 0.5f * x;
    return fmaf(hx, th, hx);
}

// ---------------- edge counting sort (128B-padded counters) ----------------
__global__ void k_zero() {
    int t = blockIdx.x * blockDim.x + threadIdx.x;
    if (t < Gg * PAD) d_hist[t] = 0;
}

__global__ void k_hist(const int* __restrict__ ei, const int* __restrict__ bidx) {
    int e = blockIdx.x * blockDim.x + threadIdx.x;
    if (e < Ee) {
        int g = bidx[ei[e]];
        d_ge[e] = g;
        atomicAdd(&d_hist[g * PAD], 1);
    }
}

__global__ void k_scan() {
    __shared__ int tmp[Gg];
    int t = threadIdx.x;
    int h = d_hist[t * PAD];
    tmp[t] = h;
    __syncthreads();
    for (int off = 1; off < Gg; off <<= 1) {
        int v = (t >= off) ? tmp[t - off] : 0;
        __syncthreads();
        tmp[t] += v;
        __syncthreads();
    }
    d_off[t + 1] = tmp[t];
    if (t == 0) d_off[0] = 0;
    d_cursor[t * PAD] = tmp[t] - h;
}

__global__ void k_scatter() {
    int e = blockIdx.x * blockDim.x + threadIdx.x;
    if (e < Ee) {
        int g = d_ge[e];
        int p = atomicAdd(&d_cursor[g * PAD], 1);
        d_eord[p] = e;
    }
}

// ---------------- fused node layer-1 + BN + GELU + segment reduce ----------------
// R13-proven structure: float4 feature tiles, bc2 at point of use.
__global__ void __launch_bounds__(256) k_node(
    const float* __restrict__ nf, const float* __restrict__ dp,
    const int* __restrict__ ny, const int* __restrict__ bidx,
    const float* __restrict__ w1, const float* __restrict__ b1,
    const float* __restrict__ g1, const float* __restrict__ be1)
{
    int g = blockIdx.x, t = threadIdx.x;
    int j0 = 2 * t;
    __shared__ u64   sw9p[9][256];
    __shared__ float4 sf4[32][8];
    __shared__ float sdp[32];
    __shared__ int   sy[32];

    const float inv = rsqrtf(1.0f + 1e-5f);
    float2 gv  = *(const float2*)&g1[j0];
    float2 bv  = *(const float2*)&b1[j0];
    float2 bev = *(const float2*)&be1[j0];
    float sA = gv.x * inv, sB = gv.y * inv;

    u64 wn[32];
#pragma unroll
    for (int k = 0; k < 32; k++) {
        float2 w = *(const float2*)&w1[k * Hh + j0];
        wn[k] = pk2(w.x * sA, w.y * sB);
    }
#pragma unroll
    for (int c = 0; c < 9; c++) {
        float2 w = *(const float2*)&w1[(32 + c) * Hh + j0];
        sw9p[c][t] = pk2(w.x * sA, w.y * sB);
    }
    u64 bj = pk2(bv.x * sA + bev.x, bv.y * sB + bev.y);

    int lo = 0, hi = Nn;
    while (lo < hi) { int m = (lo + hi) >> 1; if (bidx[m] < g) lo = m + 1; else hi = m; }
    int s0i = lo;
    hi = Nn;
    while (lo < hi) { int m = (lo + hi) >> 1; if (bidx[m] < g + 1) lo = m + 1; else hi = m; }
    int s1i = lo;

    u64 acc2 = 0;
    for (int base = s0i; base < s1i; base += 32) {
        int cnt = min(32, s1i - base);
        __syncthreads();
        {
            int row = t >> 3, q = t & 7;
            if (row < cnt)
                sf4[row][q] = ((const float4*)nf)[(base + row) * 8 + q];
            if (t < cnt) { sdp[t] = dp[base + t]; sy[t] = ny[base + t]; }
        }
        __syncthreads();
        for (int n = 0; n < cnt; n++) {
            u64 a0 = bj, a1 = 0, a2 = 0, a3 = 0;
#pragma unroll
            for (int q = 0; q < 8; q += 4) {
                float4 v0 = sf4[n][q + 0];
                float4 v1 = sf4[n][q + 1];
                float4 v2 = sf4[n][q + 2];
                float4 v3 = sf4[n][q + 3];
                int k = q * 4;
                a0 = fma2(bc2(v0.x), wn[k + 0],  a0);
                a1 = fma2(bc2(v0.y), wn[k + 1],  a1);
                a2 = fma2(bc2(v0.z), wn[k + 2],  a2);
                a3 = fma2(bc2(v0.w), wn[k + 3],  a3);
                a0 = fma2(bc2(v1.x), wn[k + 4],  a0);
                a1 = fma2(bc2(v1.y), wn[k + 5],  a1);
                a2 = fma2(bc2(v1.z), wn[k + 6],  a2);
                a3 = fma2(bc2(v1.w), wn[k + 7],  a3);
                a0 = fma2(bc2(v2.x), wn[k + 8],  a0);
                a1 = fma2(bc2(v2.y), wn[k + 9],  a1);
                a2 = fma2(bc2(v2.z), wn[k + 10], a2);
                a3 = fma2(bc2(v2.w), wn[k + 11], a3);
                a0 = fma2(bc2(v3.x), wn[k + 12], a0);
                a1 = fma2(bc2(v3.y), wn[k + 13], a1);
                a2 = fma2(bc2(v3.z), wn[k + 14], a2);
                a3 = fma2(bc2(v3.w), wn[k + 15], a3);
            }
            a0 = fma2(bc2(sdp[n]), sw9p[sy[n]][t], a0);
            u64 x2 = add2(add2(a0, a1), add2(a2, a3));
            acc2 = add2(acc2, gelu2(x2));
        }
    }
    float r0, r1; up2(acc2, r0, r1);
    *(float2*)&d_Sn[g * Hh + j0] = make_float2(r0, r1);
    if (t == 0) d_cntn[g] = s1i - s0i;
}

// ---------------- fused edge layer-1 + BN + GELU + segment reduce ----------------
// 2-way unrolled element loop: two independent FFMA2 + GELU chains in flight.
__global__ void __launch_bounds__(256) k_edge(
    const float* __restrict__ ef,
    const float* __restrict__ w1, const float* __restrict__ b1,
    const float* __restrict__ g1, const float* __restrict__ be1)
{
    int g = blockIdx.x, t = threadIdx.x;
    int j0 = 2 * t;
    __shared__ float4 se4[64][4];

    const float inv = rsqrtf(1.0f + 1e-5f);
    float2 gv  = *(const float2*)&g1[j0];
    float2 bv  = *(const float2*)&b1[j0];
    float2 bev = *(const float2*)&be1[j0];
    float sA = gv.x * inv, sB = gv.y * inv;

    u64 we[16];
#pragma unroll
    for (int k = 0; k < 16; k++) {
        float2 w = *(const float2*)&w1[k * Hh + j0];
        we[k] = pk2(w.x * sA, w.y * sB);
    }
    u64 bj = pk2(bv.x * sA + bev.x, bv.y * sB + bev.y);

    int s0i = d_off[g], s1i = d_off[g + 1];
    u64 acc2 = 0;
    for (int base = s0i; base < s1i; base += 64) {
        int cnt = min(64, s1i - base);
        __syncthreads();
        {
            int row = t >> 2, q = t & 3;
            if (row < cnt)
                se4[row][q] = ((const float4*)ef)[d_eord[base + row] * 4 + q];
        }
        __syncthreads();
        int n = 0;
        for (; n + 2 <= cnt; n += 2) {
            u64 a0 = bj, a1 = 0, b0 = bj, b1_ = 0;
#pragma unroll
            for (int q = 0; q < 4; q += 2) {
                float4 vA0 = se4[n][q];
                float4 vA1 = se4[n][q + 1];
                float4 vB0 = se4[n + 1][q];
                float4 vB1 = se4[n + 1][q + 1];
                int k = q * 4;
                a0  = fma2(bc2(vA0.x), we[k + 0], a0);
                a1  = fma2(bc2(vA0.y), we[k + 1], a1);
                b0  = fma2(bc2(vB0.x), we[k + 0], b0);
                b1_ = fma2(bc2(vB0.y), we[k + 1], b1_);
                a0  = fma2(bc2(vA0.z), we[k + 2], a0);
                a1  = fma2(bc2(vA0.w), we[k + 3], a1);
                b0  = fma2(bc2(vB0.z), we[k + 2], b0);
                b1_ = fma2(bc2(vB0.w), we[k + 3], b1_);
                a0  = fma2(bc2(vA1.x), we[k + 4], a0);
                a1  = fma2(bc2(vA1.y), we[k + 5], a1);
                b0  = fma2(bc2(vB1.x), we[k + 4], b0);
                b1_ = fma2(bc2(vB1.y), we[k + 5], b1_);
                a0  = fma2(bc2(vA1.z), we[k + 6], a0);
                a1  = fma2(bc2(vA1.w), we[k + 7], a1);
                b0  = fma2(bc2(vB1.z), we[k + 6], b0);
                b1_ = fma2(bc2(vB1.w), we[k + 7], b1_);
            }
            u64 tA = add2(a0, a1);
            u64 tB = add2(b0, b1_);
            acc2 = add2(acc2, gelu2(tA));
            acc2 = add2(acc2, gelu2(tB));
        }
        for (; n < cnt; n++) {
            float4 v0 = se4[n][0];
            float4 v1 = se4[n][1];
            float4 v2 = se4[n][2];
            float4 v3 = se4[n][3];
            u64 a0 = bj, a1 = 0;
            a0 = fma2(bc2(v0.x), we[0],  a0);
            a1 = fma2(bc2(v0.y), we[1],  a1);
            a0 = fma2(bc2(v0.z), we[2],  a0);
            a1 = fma2(bc2(v0.w), we[3],  a1);
            a0 = fma2(bc2(v1.x), we[4],  a0);
            a1 = fma2(bc2(v1.y), we[5],  a1);
            a0 = fma2(bc2(v1.z), we[6],  a0);
            a1 = fma2(bc2(v1.w), we[7],  a1);
            a0 = fma2(bc2(v2.x), we[8],  a0);
            a1 = fma2(bc2(v2.y), we[9],  a1);
            a0 = fma2(bc2(v2.z), we[10], a0);
            a1 = fma2(bc2(v2.w), we[11], a1);
            a0 = fma2(bc2(v3.x), we[12], a0);
            a1 = fma2(bc2(v3.y), we[13], a1);
            a0 = fma2(bc2(v3.z), we[14], a0);
            a1 = fma2(bc2(v3.w), we[15], a1);
            acc2 = add2(acc2, gelu2(add2(a0, a1)));
        }
    }
    float r0, r1; up2(acc2, r0, r1);
    *(float2*)&d_Se[g * Hh + j0] = make_float2(r0, r1);
}

// ---------------- graph-level dual GEMM ----------------
__global__ void __launch_bounds__(256) k_t1(
    const float* __restrict__ gf,
    const float* __restrict__ nfw2, const float* __restrict__ nfb2,
    const float* __restrict__ efw2, const float* __restrict__ efb2)
{
    __shared__ float As[16][64];
    __shared__ float Bs[16][64];
    int row0 = blockIdx.y * 64, col0 = blockIdx.x * 64;
    int tid = threadIdx.x, ty = tid >> 4, tx = tid & 15;
    float acc[4][4] = {};

    for (int pass = 0; pass < 2; pass++) {
        const float* A = pass ? d_Se : d_Sn;
        const float* B = pass ? efw2 : nfw2;
        for (int k0 = 0; k0 < Hh; k0 += 16) {
#pragma unroll
            for (int i = 0; i < 4; i++) {
                int idx = tid + i * 256;
                int r = idx >> 4, kk = idx & 15;
                As[kk][r] = A[(row0 + r) * Hh + k0 + kk];
                int kb = idx >> 6, c = idx & 63;
                Bs[kb][c] = B[(k0 + kb) * Hh + col0 + c];
            }
            __syncthreads();
#pragma unroll
            for (int kk = 0; kk < 16; kk++) {
                float av[4], bv[4];
#pragma unroll
                for (int i = 0; i < 4; i++) av[i] = As[kk][ty * 4 + i];
#pragma unroll
                for (int jx = 0; jx < 4; jx++) bv[jx] = Bs[kk][tx * 4 + jx];
#pragma unroll
                for (int i = 0; i < 4; i++)
#pragma unroll
                    for (int jx = 0; jx < 4; jx++) acc[i][jx] += av[i] * bv[jx];
            }
            __syncthreads();
        }
    }
#pragma unroll
    for (int i = 0; i < 4; i++) {
        int r = row0 + ty * 4 + i;
        float cn = (float)d_cntn[r];
        float ce = (float)(d_off[r + 1] - d_off[r]);
#pragma unroll
        for (int jx = 0; jx < 4; jx++) {
            int c = col0 + tx * 4 + jx;
            d_T1[r * Hh + c] = acc[i][jx] + gf[r * Hh + c] + cn * nfb2[c] + ce * efb2[c];
        }
    }
}

// ---------------- graph MLP block ----------------
__global__ void __launch_bounds__(256) k_mlp(
    int stage,
    const float* __restrict__ W, const float* __restrict__ b,
    const float* __restrict__ gm, const float* __restrict__ be)
{
    const float* A = (stage == 0) ? d_T1 : d_X1;
    float* out = (stage == 0) ? d_X1 : d_X2;

    __shared__ float As[16][64];
    __shared__ float Bs[16][64];
    int row0 = blockIdx.y * 64, col0 = blockIdx.x * 64;
    int tid = threadIdx.x, ty = tid >> 4, tx = tid & 15;
    float acc[4][4] = {};

    for (int k0 = 0; k0 < Hh; k0 += 16) {
#pragma unroll
        for (int i = 0; i < 4; i++) {
            int idx = tid + i * 256;
            int r = idx >> 4, kk = idx & 15;
            As[kk][r] = A[(row0 + r) * Hh + k0 + kk];
            int kb = idx >> 6, c = idx & 63;
            Bs[kb][c] = W[(k0 + kb) * Hh + col0 + c];
        }
        __syncthreads();
#pragma unroll
        for (int kk = 0; kk < 16; kk++) {
            float av[4], bv[4];
#pragma unroll
            for (int i = 0; i < 4; i++) av[i] = As[kk][ty * 4 + i];
#pragma unroll
            for (int jx = 0; jx < 4; jx++) bv[jx] = Bs[kk][tx * 4 + jx];
#pragma unroll
            for (int i = 0; i < 4; i++)
#pragma unroll
                for (int jx = 0; jx < 4; jx++) acc[i][jx] += av[i] * bv[jx];
        }
        __syncthreads();
    }
#pragma unroll
    for (int i = 0; i < 4; i++) {
        int r = row0 + ty * 4 + i;
#pragma unroll
        for (int jx = 0; jx < 4; jx++) {
            int c = col0 + tx * 4 + jx;
            float s = gm[c] * rsqrtf(1.0f + 1e-5f);
            float v = acc[i][jx] * s + b[c] * s + be[c];
            out[r * Hh + c] = gelu_f(v);
        }
    }
}

// ---------------- final Linear 512 -> 2 ----------------
__global__ void __launch_bounds__(256) k_out(
    const float* __restrict__ w3, const float* __restrict__ b3, float* __restrict__ out)
{
    int warp = (blockIdx.x * blockDim.x + threadIdx.x) >> 5;
    int lane = threadIdx.x & 31;
    if (warp >= Gg * 2) return;
    int g = warp >> 1, c = warp & 1;
    const float* x = &d_X2[g * Hh];
    float acc = 0.0f;
    for (int k = lane; k < Hh; k += 32) acc += x[k] * w3[k * 2 + c];
#pragma unroll
    for (int o = 16; o; o >>= 1) acc += __shfl_down_sync(0xffffffffu, acc, o);
    if (lane == 0) out[g * 2 + c] = acc + b3[c];
}

// ---------------- launch ----------------
extern "C" void kernel_launch(void* const* d_in, const int* in_sizes, int n_in,
                              void* d_out, int out_size)
{
    const float* nf    = (const float*)d_in[0];
    const float* ef    = (const float*)d_in[1];
    const float* gf    = (const float*)d_in[2];
    const float* dp    = (const float*)d_in[3];
    const int*   ny    = (const int*)d_in[4];
    const int*   bidx  = (const int*)d_in[5];
    const int*   ei    = (const int*)d_in[6];
    const float* nfw1  = (const float*)d_in[7];
    const float* nfb1  = (const float*)d_in[8];
    const float* nfg1  = (const float*)d_in[9];
    const float* nfbe1 = (const float*)d_in[10];
    const float* nfw2  = (const float*)d_in[11];
    const float* nfb2  = (const float*)d_in[12];
    const float* efw1  = (const float*)d_in[13];
    const float* efb1  = (const float*)d_in[14];
    const float* efg1  = (const float*)d_in[15];
    const float* efbe1 = (const float*)d_in[16];
    const float* efw2  = (const float*)d_in[17];
    const float* efb2  = (const float*)d_in[18];
    const float* ow1   = (const float*)d_in[19];
    const float* ob1   = (const float*)d_in[20];
    const float* og1   = (const float*)d_in[21];
    const float* obe1  = (const float*)d_in[22];
    const float* ow2   = (const float*)d_in[23];
    const float* ob2   = (const float*)d_in[24];
    const float* og2   = (const float*)d_in[25];
    const float* obe2  = (const float*)d_in[26];
    const float* ow3   = (const float*)d_in[27];
    const float* ob3   = (const float*)d_in[28];
    float* out = (float*)d_out;

    k_zero<<<(Gg * PAD + 255) / 256, 256>>>();
    k_hist<<<(Ee + 255) / 256, 256>>>(ei, bidx);
    k_scan<<<1, Gg>>>();
    k_scatter<<<(Ee + 255) / 256, 256>>>();

    k_node<<<Gg, 256>>>(nf, dp, ny, bidx, nfw1, nfb1, nfg1, nfbe1);
    k_edge<<<Gg, 256>>>(ef, efw1, efb1, efg1, efbe1);

    dim3 gdim(Hh / 64, Gg / 64);
    k_t1<<<gdim, 256>>>(gf, nfw2, nfb2, efw2, efb2);
    k_mlp<<<gdim, 256>>>(0, ow1, ob1, og1, obe1);
    k_mlp<<<gdim, 256>>>(1, ow2, ob2, og2, obe2);
    k_out<<<(Gg * 2 * 32) / 256, 256>>>(ow3, ob3, out);
}